// round 3
// baseline (speedup 1.0000x reference)
#include <cuda_runtime.h>

#define NDIM 8192
#define MDIM 4096
#define CDIM 1024
#define ADIM 256
#define XDIM 1280
#define GRID_D 148
#define ROWS_PER 56   // ceil(8192/148)

// Scratch (static device globals — no runtime allocation)
__device__ float g_h[CDIM];
__device__ float g_rw[NDIM];
__device__ float g_partial[GRID_D * MDIM];

// ---------------------------------------------------------------------------
// Kernel A: GRU cell. One block per output channel c (1024 blocks, 256 thr).
// Computes 6 dot products (3 input-gates over 1280, 3 hidden-gates over 1024),
// then the gate math. Writes h to g_h and to the output tail.
// ---------------------------------------------------------------------------
__global__ void __launch_bounds__(256) gru_kernel(
    const float* __restrict__ action, const float* __restrict__ hid,
    const float* __restrict__ hprev,
    const float* __restrict__ W_ih, const float* __restrict__ W_hh,
    const float* __restrict__ b_ih, const float* __restrict__ b_hh,
    float* __restrict__ out)
{
    int c = blockIdx.x, t = threadIdx.x;
    const float* wr_i = W_ih + (size_t)c * XDIM;
    const float* wz_i = W_ih + (size_t)(c + CDIM) * XDIM;
    const float* wn_i = W_ih + (size_t)(c + 2 * CDIM) * XDIM;
    const float* wr_h = W_hh + (size_t)c * CDIM;
    const float* wz_h = W_hh + (size_t)(c + CDIM) * CDIM;
    const float* wn_h = W_hh + (size_t)(c + 2 * CDIM) * CDIM;

    float s0 = 0.f, s1 = 0.f, s2 = 0.f, s3 = 0.f, s4 = 0.f, s5 = 0.f;
    for (int k = t; k < XDIM; k += 256) {
        float xv = (k < ADIM) ? action[k] : hid[k - ADIM];
        s0 += wr_i[k] * xv;
        s1 += wz_i[k] * xv;
        s2 += wn_i[k] * xv;
    }
    for (int k = t; k < CDIM; k += 256) {
        float hv = hprev[k];
        s3 += wr_h[k] * hv;
        s4 += wz_h[k] * hv;
        s5 += wn_h[k] * hv;
    }

    __shared__ float sm[6][256];
    sm[0][t] = s0; sm[1][t] = s1; sm[2][t] = s2;
    sm[3][t] = s3; sm[4][t] = s4; sm[5][t] = s5;
    __syncthreads();
    for (int off = 128; off > 0; off >>= 1) {
        if (t < off) {
#pragma unroll
            for (int j = 0; j < 6; j++) sm[j][t] += sm[j][t + off];
        }
        __syncthreads();
    }

    if (t == 0) {
        float gr  = sm[0][0] + b_ih[c]            + sm[3][0] + b_hh[c];
        float gz  = sm[1][0] + b_ih[CDIM + c]     + sm[4][0] + b_hh[CDIM + c];
        float gin = sm[2][0] + b_ih[2 * CDIM + c];
        float ghn = sm[5][0] + b_hh[2 * CDIM + c];
        float r = 1.f / (1.f + expf(-gr));
        float z = 1.f / (1.f + expf(-gz));
        float n = tanhf(gin + r * ghn);
        float h = (1.f - z) * n + z * hprev[c];
        g_h[c] = h;
        out[MDIM + 2 * NDIM + c] = h;   // new_controller_hidden
    }
}

// ---------------------------------------------------------------------------
// Kernel B: gate + gamma scalars, then sharpened read/write weights.
// Cosine-sim weights are identically 1.0 (softmax over size-1 axis) and the
// circular-conv scalar cancels in sharpen, so:
//   w_i = pow(g + (1-g)*prev_i, gamma) / sum
// ---------------------------------------------------------------------------
__global__ void __launch_bounds__(1024) weights_kernel(
    const float* __restrict__ prev_r, const float* __restrict__ prev_w,
    const float* __restrict__ W_gamma, const float* __restrict__ b_gamma,
    const float* __restrict__ W_gate, const float* __restrict__ b_gate,
    float* __restrict__ out)
{
    int t = threadIdx.x;
    __shared__ float sa[1024], sb[1024];
    __shared__ float s_gate, s_gamma;

    float h = g_h[t];
    sa[t] = W_gate[t] * h;
    sb[t] = W_gamma[t] * h;
    __syncthreads();
    for (int off = 512; off > 0; off >>= 1) {
        if (t < off) { sa[t] += sa[t + off]; sb[t] += sb[t + off]; }
        __syncthreads();
    }
    if (t == 0) {
        s_gate = 1.f / (1.f + expf(-(sa[0] + b_gate[0])));
        float x = sb[0] + b_gamma[0];
        s_gamma = (x > 20.f) ? x : log1pf(expf(x));   // softplus
    }
    __syncthreads();
    float gate = s_gate, gamma = s_gamma;

    float pr[8], pw[8];
    float sumr = 0.f, sumw = 0.f;
#pragma unroll
    for (int j = 0; j < 8; j++) {
        int i = t + j * 1024;
        float vr = gate + (1.f - gate) * prev_r[i];
        float vw = gate + (1.f - gate) * prev_w[i];
        pr[j] = powf(vr, gamma);
        pw[j] = powf(vw, gamma);
        sumr += pr[j];
        sumw += pw[j];
    }
    sa[t] = sumr; sb[t] = sumw;
    __syncthreads();
    for (int off = 512; off > 0; off >>= 1) {
        if (t < off) { sa[t] += sa[t + off]; sb[t] += sb[t + off]; }
        __syncthreads();
    }
    float invr = 1.f / sa[0], invw = 1.f / sb[0];
#pragma unroll
    for (int j = 0; j < 8; j++) {
        int i = t + j * 1024;
        float wr = pr[j] * invr;
        g_rw[i] = wr;
        out[MDIM + i] = wr;                  // read_weight
        out[MDIM + NDIM + i] = pw[j] * invw; // write_weight
    }
}

// ---------------------------------------------------------------------------
// Kernel C: read_vector = rw^T @ memory, split over rows.
// 148 blocks x 1024 threads; each thread owns 4 columns (float4). Unroll-by-2
// with independent loads to keep >=2 16B loads in flight per thread.
// ---------------------------------------------------------------------------
__global__ void __launch_bounds__(1024) gemv_kernel(const float* __restrict__ mem)
{
    int c4 = threadIdx.x;                      // float4 column group 0..1023
    int r0 = blockIdx.x * ROWS_PER;
    int r1 = r0 + ROWS_PER;
    if (r1 > NDIM) r1 = NDIM;

    const float4* m4 = (const float4*)mem + c4;
    float4 acc0 = make_float4(0.f, 0.f, 0.f, 0.f);
    float4 acc1 = make_float4(0.f, 0.f, 0.f, 0.f);

    int i = r0;
    for (; i + 1 < r1; i += 2) {
        float w0 = g_rw[i];
        float w1 = g_rw[i + 1];
        float4 v0 = m4[(size_t)i * (MDIM / 4)];
        float4 v1 = m4[(size_t)(i + 1) * (MDIM / 4)];
        acc0.x += w0 * v0.x; acc0.y += w0 * v0.y;
        acc0.z += w0 * v0.z; acc0.w += w0 * v0.w;
        acc1.x += w1 * v1.x; acc1.y += w1 * v1.y;
        acc1.z += w1 * v1.z; acc1.w += w1 * v1.w;
    }
    if (i < r1) {
        float w0 = g_rw[i];
        float4 v0 = m4[(size_t)i * (MDIM / 4)];
        acc0.x += w0 * v0.x; acc0.y += w0 * v0.y;
        acc0.z += w0 * v0.z; acc0.w += w0 * v0.w;
    }
    acc0.x += acc1.x; acc0.y += acc1.y; acc0.z += acc1.z; acc0.w += acc1.w;
    ((float4*)g_partial)[(size_t)blockIdx.x * (MDIM / 4) + c4] = acc0;
}

// ---------------------------------------------------------------------------
// Kernel D: reduce partials into read_vector (fixed order -> deterministic).
// 1024 threads x 1 block-group; float4 across the 4096 columns.
// ---------------------------------------------------------------------------
__global__ void __launch_bounds__(256) reduce_kernel(float* __restrict__ out)
{
    int c4 = blockIdx.x * 256 + threadIdx.x;   // 0..1023 (float4 groups)
    const float4* p4 = (const float4*)g_partial + c4;
    float4 s = make_float4(0.f, 0.f, 0.f, 0.f);
#pragma unroll 4
    for (int r = 0; r < GRID_D; r++) {
        float4 v = p4[(size_t)r * (MDIM / 4)];
        s.x += v.x; s.y += v.y; s.z += v.z; s.w += v.w;
    }
    ((float4*)out)[c4] = s;                    // read_vector
}

extern "C" void kernel_launch(void* const* d_in, const int* in_sizes, int n_in,
                              void* d_out, int out_size)
{
    const float* action  = (const float*)d_in[0];   // (1,256)
    const float* hid     = (const float*)d_in[1];   // (1,1,1024)
    const float* prev_r  = (const float*)d_in[2];   // (8192,1)
    const float* prev_w  = (const float*)d_in[3];   // (8192,1)
    const float* hprev   = (const float*)d_in[4];   // (1,1,1024)
    const float* memory  = (const float*)d_in[5];   // (8192,4096)
    const float* W_ih    = (const float*)d_in[6];   // (3072,1280)
    const float* W_hh    = (const float*)d_in[7];   // (3072,1024)
    const float* b_ih    = (const float*)d_in[8];
    const float* b_hh    = (const float*)d_in[9];
    // d_in[10..19]: W_read/b_read/W_write/b_write/W_add/b_add/W_erase/b_erase/
    //               W_shift/b_shift — dead code (cosine-sim == 1, circ-conv
    //               scalar cancels in sharpen, memory write discarded)
    const float* W_gamma = (const float*)d_in[20];
    const float* b_gamma = (const float*)d_in[21];
    const float* W_gate  = (const float*)d_in[22];
    const float* b_gate  = (const float*)d_in[23];

    float* out = (float*)d_out;
    // Layout: [0:4096) read_vector | [4096:12288) read_weight |
    //         [12288:20480) write_weight | [20480:21504) new_controller_hidden

    gru_kernel<<<CDIM, 256>>>(action, hid, hprev, W_ih, W_hh, b_ih, b_hh, out);
    weights_kernel<<<1, 1024>>>(prev_r, prev_w, W_gamma, b_gamma, W_gate, b_gate, out);
    gemv_kernel<<<GRID_D, 1024>>>(memory);
    reduce_kernel<<<MDIM / 1024, 256>>>(out);
}

// round 4
// speedup vs baseline: 1.2142x; 1.2142x over previous
#include <cuda_runtime.h>

#define NDIM 8192
#define MDIM 4096
#define CDIM 1024
#define ADIM 256
#define XDIM 1280

// Scratch (static device globals — no runtime allocation)
__device__ float g_h[CDIM];
__device__ float g_rw[NDIM];

// ---------------------------------------------------------------------------
// Kernel A: GRU cell. One block per output channel c (1024 blocks, 256 thr).
// 6 dot products (3 input-gates over 1280, 3 hidden-gates over 1024) + gate
// math. Writes h to g_h and to the output tail.
// ---------------------------------------------------------------------------
__global__ void __launch_bounds__(256) gru_kernel(
    const float* __restrict__ action, const float* __restrict__ hid,
    const float* __restrict__ hprev,
    const float* __restrict__ W_ih, const float* __restrict__ W_hh,
    const float* __restrict__ b_ih, const float* __restrict__ b_hh,
    float* __restrict__ out)
{
    int c = blockIdx.x, t = threadIdx.x;
    const float* wr_i = W_ih + (size_t)c * XDIM;
    const float* wz_i = W_ih + (size_t)(c + CDIM) * XDIM;
    const float* wn_i = W_ih + (size_t)(c + 2 * CDIM) * XDIM;
    const float* wr_h = W_hh + (size_t)c * CDIM;
    const float* wz_h = W_hh + (size_t)(c + CDIM) * CDIM;
    const float* wn_h = W_hh + (size_t)(c + 2 * CDIM) * CDIM;

    float s0 = 0.f, s1 = 0.f, s2 = 0.f, s3 = 0.f, s4 = 0.f, s5 = 0.f;
#pragma unroll 5
    for (int k = t; k < XDIM; k += 256) {
        float xv = (k < ADIM) ? action[k] : hid[k - ADIM];
        s0 += wr_i[k] * xv;
        s1 += wz_i[k] * xv;
        s2 += wn_i[k] * xv;
    }
#pragma unroll 4
    for (int k = t; k < CDIM; k += 256) {
        float hv = hprev[k];
        s3 += wr_h[k] * hv;
        s4 += wz_h[k] * hv;
        s5 += wn_h[k] * hv;
    }

    __shared__ float sm[6][256];
    sm[0][t] = s0; sm[1][t] = s1; sm[2][t] = s2;
    sm[3][t] = s3; sm[4][t] = s4; sm[5][t] = s5;
    __syncthreads();
    for (int off = 128; off > 0; off >>= 1) {
        if (t < off) {
#pragma unroll
            for (int j = 0; j < 6; j++) sm[j][t] += sm[j][t + off];
        }
        __syncthreads();
    }

    if (t == 0) {
        float gr  = sm[0][0] + b_ih[c]            + sm[3][0] + b_hh[c];
        float gz  = sm[1][0] + b_ih[CDIM + c]     + sm[4][0] + b_hh[CDIM + c];
        float gin = sm[2][0] + b_ih[2 * CDIM + c];
        float ghn = sm[5][0] + b_hh[2 * CDIM + c];
        float r = 1.f / (1.f + expf(-gr));
        float z = 1.f / (1.f + expf(-gz));
        float n = tanhf(gin + r * ghn);
        float h = (1.f - z) * n + z * hprev[c];
        g_h[c] = h;
        out[MDIM + 2 * NDIM + c] = h;   // new_controller_hidden
    }
}

// ---------------------------------------------------------------------------
// Kernel B: gate + gamma scalars, then sharpened read/write weights.
// Cosine-sim weights are identically 1.0 (softmax over size-1 axis) and the
// circular-conv scalar cancels in sharpen, so:
//   w_i = pow(g + (1-g)*prev_i, gamma) / sum
// ---------------------------------------------------------------------------
__global__ void __launch_bounds__(1024) weights_kernel(
    const float* __restrict__ prev_r, const float* __restrict__ prev_w,
    const float* __restrict__ W_gamma, const float* __restrict__ b_gamma,
    const float* __restrict__ W_gate, const float* __restrict__ b_gate,
    float* __restrict__ out)
{
    int t = threadIdx.x;
    __shared__ float sa[1024], sb[1024];
    __shared__ float s_gate, s_gamma;

    float h = g_h[t];
    sa[t] = W_gate[t] * h;
    sb[t] = W_gamma[t] * h;
    __syncthreads();
    for (int off = 512; off > 0; off >>= 1) {
        if (t < off) { sa[t] += sa[t + off]; sb[t] += sb[t + off]; }
        __syncthreads();
    }
    if (t == 0) {
        s_gate = 1.f / (1.f + expf(-(sa[0] + b_gate[0])));
        float x = sb[0] + b_gamma[0];
        s_gamma = (x > 20.f) ? x : log1pf(expf(x));   // softplus
    }
    __syncthreads();
    float gate = s_gate, gamma = s_gamma;

    float pr[8], pw[8];
    float sumr = 0.f, sumw = 0.f;
#pragma unroll
    for (int j = 0; j < 8; j++) {
        int i = t + j * 1024;
        float vr = gate + (1.f - gate) * prev_r[i];
        float vw = gate + (1.f - gate) * prev_w[i];
        pr[j] = powf(vr, gamma);
        pw[j] = powf(vw, gamma);
        sumr += pr[j];
        sumw += pw[j];
    }
    sa[t] = sumr; sb[t] = sumw;
    __syncthreads();
    for (int off = 512; off > 0; off >>= 1) {
        if (t < off) { sa[t] += sa[t + off]; sb[t] += sb[t + off]; }
        __syncthreads();
    }
    float invr = 1.f / sa[0], invw = 1.f / sb[0];
#pragma unroll
    for (int j = 0; j < 8; j++) {
        int i = t + j * 1024;
        float wr = pr[j] * invr;
        g_rw[i] = wr;
        out[MDIM + i] = wr;                  // read_weight
        out[MDIM + NDIM + i] = pw[j] * invw; // write_weight
    }
}

// ---------------------------------------------------------------------------
// Kernel C (fused GEMV): read_vector = rw^T @ memory, column-split.
// 128 blocks x 1024 threads. Block b owns columns [b*32, b*32+32).
// Thread = (c4 = tid&7, slice = tid>>3); each thread accumulates 64 rows of
// its float4 column group, then a fixed-order shared-memory tree reduces the
// 128 slices. No DRAM partials, no second kernel, deterministic.
// ---------------------------------------------------------------------------
__global__ void __launch_bounds__(1024) gemv_kernel(
    const float* __restrict__ mem, float* __restrict__ out)
{
    int c4    = threadIdx.x & 7;     // 0..7   (float4 column group in block)
    int slice = threadIdx.x >> 3;    // 0..127 (row slice)
    int g4    = blockIdx.x * 8 + c4; // global float4 column group 0..1023

    const float4* m4 = (const float4*)mem + g4;
    int r0 = slice * 64;

    float4 acc = make_float4(0.f, 0.f, 0.f, 0.f);
#pragma unroll 4
    for (int i = 0; i < 64; i++) {
        int r = r0 + i;
        float w  = g_rw[r];                       // warp broadcast
        float4 v = m4[(size_t)r * (MDIM / 4)];
        acc.x += w * v.x;
        acc.y += w * v.y;
        acc.z += w * v.z;
        acc.w += w * v.w;
    }

    __shared__ float4 sm[128][8];                 // 16 KB
    sm[slice][c4] = acc;
    __syncthreads();
    for (int off = 64; off > 0; off >>= 1) {
        if (slice < off) {
            float4 a = sm[slice][c4];
            float4 b = sm[slice + off][c4];
            a.x += b.x; a.y += b.y; a.z += b.z; a.w += b.w;
            sm[slice][c4] = a;
        }
        __syncthreads();
    }
    if (slice == 0)
        ((float4*)out)[g4] = sm[0][c4];           // read_vector
}

extern "C" void kernel_launch(void* const* d_in, const int* in_sizes, int n_in,
                              void* d_out, int out_size)
{
    const float* action  = (const float*)d_in[0];   // (1,256)
    const float* hid     = (const float*)d_in[1];   // (1,1,1024)
    const float* prev_r  = (const float*)d_in[2];   // (8192,1)
    const float* prev_w  = (const float*)d_in[3];   // (8192,1)
    const float* hprev   = (const float*)d_in[4];   // (1,1,1024)
    const float* memory  = (const float*)d_in[5];   // (8192,4096)
    const float* W_ih    = (const float*)d_in[6];   // (3072,1280)
    const float* W_hh    = (const float*)d_in[7];   // (3072,1024)
    const float* b_ih    = (const float*)d_in[8];
    const float* b_hh    = (const float*)d_in[9];
    // d_in[10..19]: W_read/b_read/W_write/b_write/W_add/b_add/W_erase/b_erase/
    //               W_shift/b_shift — dead code (cosine-sim == 1, circ-conv
    //               scalar cancels in sharpen, memory write discarded)
    const float* W_gamma = (const float*)d_in[20];
    const float* b_gamma = (const float*)d_in[21];
    const float* W_gate  = (const float*)d_in[22];
    const float* b_gate  = (const float*)d_in[23];

    float* out = (float*)d_out;
    // Layout: [0:4096) read_vector | [4096:12288) read_weight |
    //         [12288:20480) write_weight | [20480:21504) new_controller_hidden

    gru_kernel<<<CDIM, 256>>>(action, hid, hprev, W_ih, W_hh, b_ih, b_hh, out);
    weights_kernel<<<1, 1024>>>(prev_r, prev_w, W_gamma, b_gamma, W_gate, b_gate, out);
    gemv_kernel<<<MDIM / 32, 1024>>>(memory, out);
}

// round 6
// speedup vs baseline: 1.2495x; 1.0291x over previous
#include <cuda_runtime.h>

#define NDIM 8192
#define MDIM 4096
#define CDIM 1024
#define ADIM 256
#define XDIM 1280
#define GRID_G 148
#define ROWS_PER 56   // ceil(8192/148)

// Scratch (static device globals — no runtime allocation)
__device__ float g_h[CDIM];
__device__ float g_rw[NDIM];
__device__ float g_partial[GRID_G * MDIM];

// ---------------------------------------------------------------------------
// Kernel A: GRU cell. One block per output channel c (1024 blocks, 256 thr).
// float4-vectorized weight loads: 3 input-gate rows (320 f4) + 3 hidden-gate
// rows (256 f4) per block. Then gate math; writes h to g_h and output tail.
// ---------------------------------------------------------------------------
__global__ void __launch_bounds__(256) gru_kernel(
    const float* __restrict__ action, const float* __restrict__ hid,
    const float* __restrict__ hprev,
    const float* __restrict__ W_ih, const float* __restrict__ W_hh,
    const float* __restrict__ b_ih, const float* __restrict__ b_hh,
    float* __restrict__ out)
{
    int c = blockIdx.x, t = threadIdx.x;
    const float4* wr_i = (const float4*)(W_ih + (size_t)c * XDIM);
    const float4* wz_i = (const float4*)(W_ih + (size_t)(c + CDIM) * XDIM);
    const float4* wn_i = (const float4*)(W_ih + (size_t)(c + 2 * CDIM) * XDIM);
    const float4* wr_h = (const float4*)(W_hh + (size_t)c * CDIM);
    const float4* wz_h = (const float4*)(W_hh + (size_t)(c + CDIM) * CDIM);
    const float4* wn_h = (const float4*)(W_hh + (size_t)(c + 2 * CDIM) * CDIM);
    const float4* a4 = (const float4*)action;   // 64 groups
    const float4* x4 = (const float4*)hid;      // 256 groups
    const float4* h4 = (const float4*)hprev;    // 256 groups

    float s0 = 0.f, s1 = 0.f, s2 = 0.f, s3 = 0.f, s4 = 0.f, s5 = 0.f;

    // input gates: XDIM/4 = 320 f4 groups, 256 threads -> 2 iterations
#pragma unroll
    for (int k4 = t; k4 < XDIM / 4; k4 += 256) {
        float4 xv = (k4 < ADIM / 4) ? a4[k4] : x4[k4 - ADIM / 4];
        float4 a = wr_i[k4], b = wz_i[k4], d = wn_i[k4];
        s0 += a.x * xv.x + a.y * xv.y + a.z * xv.z + a.w * xv.w;
        s1 += b.x * xv.x + b.y * xv.y + b.z * xv.z + b.w * xv.w;
        s2 += d.x * xv.x + d.y * xv.y + d.z * xv.z + d.w * xv.w;
    }
    // hidden gates: CDIM/4 = 256 f4 groups -> exactly 1 iteration
    {
        int k4 = t;
        float4 hv = h4[k4];
        float4 a = wr_h[k4], b = wz_h[k4], d = wn_h[k4];
        s3 += a.x * hv.x + a.y * hv.y + a.z * hv.z + a.w * hv.w;
        s4 += b.x * hv.x + b.y * hv.y + b.z * hv.z + b.w * hv.w;
        s5 += d.x * hv.x + d.y * hv.y + d.z * hv.z + d.w * hv.w;
    }

    __shared__ float sm[6][256];
    sm[0][t] = s0; sm[1][t] = s1; sm[2][t] = s2;
    sm[3][t] = s3; sm[4][t] = s4; sm[5][t] = s5;
    __syncthreads();
    for (int off = 128; off > 0; off >>= 1) {
        if (t < off) {
#pragma unroll
            for (int j = 0; j < 6; j++) sm[j][t] += sm[j][t + off];
        }
        __syncthreads();
    }

    if (t == 0) {
        float gr  = sm[0][0] + b_ih[c]            + sm[3][0] + b_hh[c];
        float gz  = sm[1][0] + b_ih[CDIM + c]     + sm[4][0] + b_hh[CDIM + c];
        float gin = sm[2][0] + b_ih[2 * CDIM + c];
        float ghn = sm[5][0] + b_hh[2 * CDIM + c];
        float r = 1.f / (1.f + expf(-gr));
        float z = 1.f / (1.f + expf(-gz));
        float n = tanhf(gin + r * ghn);
        float h = (1.f - z) * n + z * hprev[c];
        g_h[c] = h;
        out[MDIM + 2 * NDIM + c] = h;   // new_controller_hidden
    }
}

// ---------------------------------------------------------------------------
// Kernel B: gate + gamma scalars, then sharpened read/write weights.
// Cosine-sim weights are identically 1.0 (softmax over size-1 axis) and the
// circular-conv scalar cancels in sharpen, so:
//   w_i = pow(g + (1-g)*prev_i, gamma) / sum
// ---------------------------------------------------------------------------
__global__ void __launch_bounds__(1024) weights_kernel(
    const float* __restrict__ prev_r, const float* __restrict__ prev_w,
    const float* __restrict__ W_gamma, const float* __restrict__ b_gamma,
    const float* __restrict__ W_gate, const float* __restrict__ b_gate,
    float* __restrict__ out)
{
    int t = threadIdx.x;
    __shared__ float sa[1024], sb[1024];
    __shared__ float s_gate, s_gamma;

    float h = g_h[t];
    sa[t] = W_gate[t] * h;
    sb[t] = W_gamma[t] * h;
    __syncthreads();
    for (int off = 512; off > 0; off >>= 1) {
        if (t < off) { sa[t] += sa[t + off]; sb[t] += sb[t + off]; }
        __syncthreads();
    }
    if (t == 0) {
        s_gate = 1.f / (1.f + expf(-(sa[0] + b_gate[0])));
        float x = sb[0] + b_gamma[0];
        s_gamma = (x > 20.f) ? x : log1pf(expf(x));   // softplus
    }
    __syncthreads();
    float gate = s_gate, gamma = s_gamma;

    float pr[8], pw[8];
    float sumr = 0.f, sumw = 0.f;
#pragma unroll
    for (int j = 0; j < 8; j++) {
        int i = t + j * 1024;
        float vr = gate + (1.f - gate) * prev_r[i];
        float vw = gate + (1.f - gate) * prev_w[i];
        pr[j] = powf(vr, gamma);
        pw[j] = powf(vw, gamma);
        sumr += pr[j];
        sumw += pw[j];
    }
    sa[t] = sumr; sb[t] = sumw;
    __syncthreads();
    for (int off = 512; off > 0; off >>= 1) {
        if (t < off) { sa[t] += sa[t + off]; sb[t] += sb[t + off]; }
        __syncthreads();
    }
    float invr = 1.f / sa[0], invw = 1.f / sb[0];
#pragma unroll
    for (int j = 0; j < 8; j++) {
        int i = t + j * 1024;
        float wr = pr[j] * invr;
        g_rw[i] = wr;
        out[MDIM + i] = wr;                  // read_weight
        out[MDIM + NDIM + i] = pw[j] * invw; // write_weight
    }
}

// ---------------------------------------------------------------------------
// Kernel C: read_vector partials = rw^T @ memory, ROW-split (streaming).
// 148 blocks x 1024 threads; block b streams rows [b*56, b*56+56): each row
// is a contiguous 16KB line read fully by the block (perfect DRAM streaming).
// Row weights staged in smem. Unroll x4 for MLP. Partials written row-major.
// ---------------------------------------------------------------------------
__global__ void __launch_bounds__(1024) gemv_kernel(const float* __restrict__ mem)
{
    int c4 = threadIdx.x;                      // float4 column group 0..1023
    int r0 = blockIdx.x * ROWS_PER;
    int r1 = r0 + ROWS_PER;
    if (r1 > NDIM) r1 = NDIM;
    int nrows = r1 - r0;
    if (nrows <= 0) return;

    __shared__ float w_s[ROWS_PER];
    if (threadIdx.x < nrows) w_s[threadIdx.x] = g_rw[r0 + threadIdx.x];
    __syncthreads();

    const float4* m4 = (const float4*)mem + (size_t)r0 * (MDIM / 4) + c4;
    float4 acc0 = make_float4(0.f, 0.f, 0.f, 0.f);
    float4 acc1 = make_float4(0.f, 0.f, 0.f, 0.f);

    int i = 0;
    for (; i + 4 <= nrows; i += 4) {
        float w0 = w_s[i], w1 = w_s[i + 1], w2 = w_s[i + 2], w3 = w_s[i + 3];
        float4 v0 = m4[(size_t)(i + 0) * (MDIM / 4)];
        float4 v1 = m4[(size_t)(i + 1) * (MDIM / 4)];
        float4 v2 = m4[(size_t)(i + 2) * (MDIM / 4)];
        float4 v3 = m4[(size_t)(i + 3) * (MDIM / 4)];
        acc0.x += w0 * v0.x; acc0.y += w0 * v0.y; acc0.z += w0 * v0.z; acc0.w += w0 * v0.w;
        acc1.x += w1 * v1.x; acc1.y += w1 * v1.y; acc1.z += w1 * v1.z; acc1.w += w1 * v1.w;
        acc0.x += w2 * v2.x; acc0.y += w2 * v2.y; acc0.z += w2 * v2.z; acc0.w += w2 * v2.w;
        acc1.x += w3 * v3.x; acc1.y += w3 * v3.y; acc1.z += w3 * v3.z; acc1.w += w3 * v3.w;
    }
    for (; i < nrows; i++) {
        float w0 = w_s[i];
        float4 v0 = m4[(size_t)i * (MDIM / 4)];
        acc0.x += w0 * v0.x; acc0.y += w0 * v0.y; acc0.z += w0 * v0.z; acc0.w += w0 * v0.w;
    }
    acc0.x += acc1.x; acc0.y += acc1.y; acc0.z += acc1.z; acc0.w += acc1.w;
    ((float4*)g_partial)[(size_t)blockIdx.x * (MDIM / 4) + c4] = acc0;
}

// ---------------------------------------------------------------------------
// Kernel D: reduce 148 partials per column (L2-resident, 2.4MB).
// 16 blocks x 1024 threads: block owns 64 f4-column-groups; thread =
// (c4_local = tid&63, slice = tid>>6). Slice sums rows slice, slice+16, ...
// then fixed-order smem tree over the 16 slices. Deterministic.
// ---------------------------------------------------------------------------
__global__ void __launch_bounds__(1024) reduce_kernel(float* __restrict__ out)
{
    int cl    = threadIdx.x & 63;              // 0..63 local f4 group
    int slice = threadIdx.x >> 6;              // 0..15
    int g4    = blockIdx.x * 64 + cl;          // global f4 group 0..1023

    const float4* p4 = (const float4*)g_partial + g4;
    float4 acc = make_float4(0.f, 0.f, 0.f, 0.f);
#pragma unroll
    for (int r = slice; r < GRID_G; r += 16) {
        float4 v = p4[(size_t)r * (MDIM / 4)];
        acc.x += v.x; acc.y += v.y; acc.z += v.z; acc.w += v.w;
    }

    __shared__ float4 sm[16][64];              // 16 KB
    sm[slice][cl] = acc;
    __syncthreads();
    for (int off = 8; off > 0; off >>= 1) {
        if (slice < off) {
            float4 a = sm[slice][cl];
            float4 b = sm[slice + off][cl];
            a.x += b.x; a.y += b.y; a.z += b.z; a.w += b.w;
            sm[slice][cl] = a;
        }
        __syncthreads();
    }
    if (slice == 0)
        ((float4*)out)[g4] = sm[0][cl];        // read_vector
}

extern "C" void kernel_launch(void* const* d_in, const int* in_sizes, int n_in,
                              void* d_out, int out_size)
{
    const float* action  = (const float*)d_in[0];   // (1,256)
    const float* hid     = (const float*)d_in[1];   // (1,1,1024)
    const float* prev_r  = (const float*)d_in[2];   // (8192,1)
    const float* prev_w  = (const float*)d_in[3];   // (8192,1)
    const float* hprev   = (const float*)d_in[4];   // (1,1,1024)
    const float* memory  = (const float*)d_in[5];   // (8192,4096)
    const float* W_ih    = (const float*)d_in[6];   // (3072,1280)
    const float* W_hh    = (const float*)d_in[7];   // (3072,1024)
    const float* b_ih    = (const float*)d_in[8];
    const float* b_hh    = (const float*)d_in[9];
    // d_in[10..19]: W_read/b_read/W_write/b_write/W_add/b_add/W_erase/b_erase/
    //               W_shift/b_shift — dead code (cosine-sim == 1, circ-conv
    //               scalar cancels in sharpen, memory write discarded)
    const float* W_gamma = (const float*)d_in[20];
    const float* b_gamma = (const float*)d_in[21];
    const float* W_gate  = (const float*)d_in[22];
    const float* b_gate  = (const float*)d_in[23];

    float* out = (float*)d_out;
    // Layout: [0:4096) read_vector | [4096:12288) read_weight |
    //         [12288:20480) write_weight | [20480:21504) new_controller_hidden

    gru_kernel<<<CDIM, 256>>>(action, hid, hprev, W_ih, W_hh, b_ih, b_hh, out);
    weights_kernel<<<1, 1024>>>(prev_r, prev_w, W_gamma, b_gamma, W_gate, b_gate, out);
    gemv_kernel<<<GRID_G, 1024>>>(memory);
    reduce_kernel<<<16, 1024>>>(out);
}

// round 9
// speedup vs baseline: 1.4741x; 1.1797x over previous
#include <cuda_runtime.h>

#define NDIM 8192
#define MDIM 4096
#define CDIM 1024
#define ADIM 256
#define XDIM 1280
#define NBLK 148
#define ROWS_PER 56

// Scratch (static device globals — no runtime allocation)
__device__ float g_dots[6 * CDIM];        // GRU gate dot products
__device__ float g_gate_part[NBLK];
__device__ float g_gamma_part[NBLK];
__device__ float g_pr[NDIM];              // unnormalized pow(read)
__device__ float g_pw[NDIM];              // unnormalized pow(write)
__device__ float g_spr[NBLK];             // per-block pow sums
__device__ float g_spw[NBLK];
__device__ float g_partial[NBLK * MDIM];  // gemv partials
__device__ unsigned g_bar1, g_bar2, g_bar3;

// Ticket barrier: never resets, correct across unlimited graph replays.
// Arrival t waits until counter reaches ((t/NBLK)+1)*NBLK.
__device__ __forceinline__ void grid_sync(unsigned* bar) {
    __syncthreads();
    if (threadIdx.x == 0) {
        __threadfence();
        unsigned t = atomicAdd(bar, 1u);
        unsigned target = (t / NBLK + 1u) * NBLK;
        while (*(volatile unsigned*)bar < target) __nanosleep(64);
    }
    __syncthreads();
    __threadfence();
}

__global__ void __launch_bounds__(1024, 1) fused_kernel(
    const float* __restrict__ action, const float* __restrict__ hid,
    const float* __restrict__ prev_r, const float* __restrict__ prev_w,
    const float* __restrict__ hprev, const float* __restrict__ mem,
    const float* __restrict__ W_ih, const float* __restrict__ W_hh,
    const float* __restrict__ b_ih, const float* __restrict__ b_hh,
    const float* __restrict__ W_gamma, const float* __restrict__ b_gamma,
    const float* __restrict__ W_gate, const float* __restrict__ b_gate,
    float* __restrict__ out)
{
    const int tid = threadIdx.x;
    const int b   = blockIdx.x;

    __shared__ float4 smt[128][8];   // 16 KB column-reduce tree
    __shared__ float  s_a[256], s_b[256];
    __shared__ float  w_s[ROWS_PER];
    __shared__ float  sh_gate, sh_gamma, sh_invSr, sh_invSw;

    // ====================== Phase 1: GRU dot products ======================
    // 6144 rows (3 input-gates over 1280, 3 hidden-gates over 1024), one warp
    // per row, float4 loads, shfl tree reduce.
    {
        const int lane = tid & 31;
        const int wg   = b * 32 + (tid >> 5);          // 0..4735
        const float4* a4 = (const float4*)action;      // 64 groups
        const float4* x4 = (const float4*)hid;         // 256 groups
        const float4* h4 = (const float4*)hprev;       // 256 groups
        for (int d = wg; d < 6 * CDIM; d += NBLK * 32) {
            float s = 0.f;
            if (d < 3 * CDIM) {
                const float4* row = (const float4*)(W_ih + (size_t)d * XDIM);
#pragma unroll
                for (int k = 0; k < 10; k++) {
                    int k4 = lane + k * 32;
                    float4 r = row[k4];
                    float4 x = (k4 < ADIM / 4) ? a4[k4] : x4[k4 - ADIM / 4];
                    s += r.x * x.x + r.y * x.y + r.z * x.z + r.w * x.w;
                }
            } else {
                const float4* row = (const float4*)(W_hh + (size_t)(d - 3 * CDIM) * CDIM);
#pragma unroll
                for (int k = 0; k < 8; k++) {
                    int k4 = lane + k * 32;
                    float4 r = row[k4];
                    float4 x = h4[k4];
                    s += r.x * x.x + r.y * x.y + r.z * x.z + r.w * x.w;
                }
            }
#pragma unroll
            for (int off = 16; off > 0; off >>= 1)
                s += __shfl_down_sync(0xffffffffu, s, off);
            if (lane == 0) g_dots[d] = s;
        }
    }
    grid_sync(&g_bar1);

    // ============ Phase 2: GRU gate math + gate/gamma partials =============
    {
        int c = b + NBLK * tid;                       // tid<7 covers all 1024
        if (tid < 8) { s_a[tid] = 0.f; s_b[tid] = 0.f; }
        __syncthreads();
        if (tid < 7 && c < CDIM) {
            float gir = g_dots[c]            + b_ih[c];
            float giz = g_dots[CDIM + c]     + b_ih[CDIM + c];
            float gin = g_dots[2 * CDIM + c] + b_ih[2 * CDIM + c];
            float ghr = g_dots[3 * CDIM + c] + b_hh[c];
            float ghz = g_dots[4 * CDIM + c] + b_hh[CDIM + c];
            float ghn = g_dots[5 * CDIM + c] + b_hh[2 * CDIM + c];
            float r = 1.f / (1.f + expf(-(gir + ghr)));
            float z = 1.f / (1.f + expf(-(giz + ghz)));
            float n = tanhf(gin + r * ghn);
            float h = (1.f - z) * n + z * hprev[c];
            out[MDIM + 2 * NDIM + c] = h;            // new_controller_hidden
            s_a[tid] = W_gate[c] * h;
            s_b[tid] = W_gamma[c] * h;
        }
        __syncthreads();
        if (tid == 0) {
            float pa = 0.f, pb = 0.f;
#pragma unroll
            for (int j = 0; j < 7; j++) { pa += s_a[j]; pb += s_b[j]; }
            g_gate_part[b] = pa;
            g_gamma_part[b] = pb;
        }
    }
    grid_sync(&g_bar2);

    // ===== Phase 3: gate/gamma finalize, pow weights, streaming GEMV =======
    // Every block computes gate/gamma identically (same fixed-order tree) so
    // results are bit-identical chip-wide.
    {
        if (tid < 256) {
            s_a[tid] = (tid < NBLK) ? g_gate_part[tid] : 0.f;
            s_b[tid] = (tid < NBLK) ? g_gamma_part[tid] : 0.f;
        }
        __syncthreads();
        for (int off = 128; off > 0; off >>= 1) {
            if (tid < off) { s_a[tid] += s_a[tid + off]; s_b[tid] += s_b[tid + off]; }
            __syncthreads();
        }
        if (tid == 0) {
            sh_gate = 1.f / (1.f + expf(-(s_a[0] + b_gate[0])));
            float x = s_b[0] + b_gamma[0];
            sh_gamma = (x > 20.f) ? x : log1pf(expf(x));   // softplus
        }
        __syncthreads();
    }

    const int r0 = b * ROWS_PER;
    int nrows = NDIM - r0;
    if (nrows > ROWS_PER) nrows = ROWS_PER;
    if (nrows < 0) nrows = 0;

    {
        float gate = sh_gate, gamma = sh_gamma;
        if (tid < nrows) {
            int r = r0 + tid;
            float vr = gate + (1.f - gate) * prev_r[r];
            float vw = gate + (1.f - gate) * prev_w[r];
            float pr = powf(vr, gamma);
            float pw = powf(vw, gamma);
            g_pr[r] = pr; g_pw[r] = pw;
            w_s[tid] = pr;              // unnormalized weights drive the gemv
            s_a[tid] = pr; s_b[tid] = pw;
        }
        __syncthreads();
        if (tid == 0) {
            float sa = 0.f, sb = 0.f;
            for (int j = 0; j < nrows; j++) { sa += s_a[j]; sb += s_b[j]; }
            g_spr[b] = sa; g_spw[b] = sb;
        }

        if (nrows > 0) {
            const float4* m4 = (const float4*)mem + (size_t)r0 * (MDIM / 4) + tid;
            float4 acc0 = make_float4(0.f, 0.f, 0.f, 0.f);
            float4 acc1 = make_float4(0.f, 0.f, 0.f, 0.f);
            int i = 0;
            for (; i + 4 <= nrows; i += 4) {
                float w0 = w_s[i], w1 = w_s[i + 1], w2 = w_s[i + 2], w3 = w_s[i + 3];
                float4 v0 = m4[(size_t)(i + 0) * (MDIM / 4)];
                float4 v1 = m4[(size_t)(i + 1) * (MDIM / 4)];
                float4 v2 = m4[(size_t)(i + 2) * (MDIM / 4)];
                float4 v3 = m4[(size_t)(i + 3) * (MDIM / 4)];
                acc0.x += w0 * v0.x; acc0.y += w0 * v0.y; acc0.z += w0 * v0.z; acc0.w += w0 * v0.w;
                acc1.x += w1 * v1.x; acc1.y += w1 * v1.y; acc1.z += w1 * v1.z; acc1.w += w1 * v1.w;
                acc0.x += w2 * v2.x; acc0.y += w2 * v2.y; acc0.z += w2 * v2.z; acc0.w += w2 * v2.w;
                acc1.x += w3 * v3.x; acc1.y += w3 * v3.y; acc1.z += w3 * v3.z; acc1.w += w3 * v3.w;
            }
            for (; i < nrows; i++) {
                float w0 = w_s[i];
                float4 v0 = m4[(size_t)i * (MDIM / 4)];
                acc0.x += w0 * v0.x; acc0.y += w0 * v0.y; acc0.z += w0 * v0.z; acc0.w += w0 * v0.w;
            }
            acc0.x += acc1.x; acc0.y += acc1.y; acc0.z += acc1.z; acc0.w += acc1.w;
            ((float4*)g_partial)[(size_t)b * (MDIM / 4) + tid] = acc0;
        } else {
            ((float4*)g_partial)[(size_t)b * (MDIM / 4) + tid] =
                make_float4(0.f, 0.f, 0.f, 0.f);
        }
    }
    grid_sync(&g_bar3);

    // ================= Phase 4: normalize + column reduce ==================
    {
        if (tid < 256) {
            s_a[tid] = (tid < NBLK) ? g_spr[tid] : 0.f;
            s_b[tid] = (tid < NBLK) ? g_spw[tid] : 0.f;
        }
        __syncthreads();
        for (int off = 128; off > 0; off >>= 1) {
            if (tid < off) { s_a[tid] += s_a[tid + off]; s_b[tid] += s_b[tid + off]; }
            __syncthreads();
        }
        if (tid == 0) { sh_invSr = 1.f / s_a[0]; sh_invSw = 1.f / s_b[0]; }
        __syncthreads();
        float invSr = sh_invSr, invSw = sh_invSw;

        // normalized weight outputs for this block's rows
        if (tid < nrows) {
            int r = r0 + tid;
            out[MDIM + r]        = g_pr[r] * invSr;  // read_weight
            out[MDIM + NDIM + r] = g_pw[r] * invSw;  // write_weight
        }

        // read_vector: blocks 0..127 each own 8 float4 column groups
        if (b < 128) {
            int cl    = tid & 7;
            int slice = tid >> 3;                    // 0..127
            int g4    = b * 8 + cl;
            const float4* p4 = (const float4*)g_partial + g4;
            float4 acc = make_float4(0.f, 0.f, 0.f, 0.f);
            for (int r = slice; r < NBLK; r += 128) {
                float4 v = p4[(size_t)r * (MDIM / 4)];
                acc.x += v.x; acc.y += v.y; acc.z += v.z; acc.w += v.w;
            }
            smt[slice][cl] = acc;
            __syncthreads();
            for (int off = 64; off > 0; off >>= 1) {
                if (slice < off) {
                    float4 a = smt[slice][cl];
                    float4 c = smt[slice + off][cl];
                    a.x += c.x; a.y += c.y; a.z += c.z; a.w += c.w;
                    smt[slice][cl] = a;
                }
                __syncthreads();
            }
            if (slice == 0) {
                float4 a = smt[0][cl];
                a.x *= invSr; a.y *= invSr; a.z *= invSr; a.w *= invSr;
                ((float4*)out)[g4] = a;              // read_vector
            }
        }
    }
}

extern "C" void kernel_launch(void* const* d_in, const int* in_sizes, int n_in,
                              void* d_out, int out_size)
{
    const float* action  = (const float*)d_in[0];   // (1,256)
    const float* hid     = (const float*)d_in[1];   // (1,1,1024)
    const float* prev_r  = (const float*)d_in[2];   // (8192,1)
    const float* prev_w  = (const float*)d_in[3];   // (8192,1)
    const float* hprev   = (const float*)d_in[4];   // (1,1,1024)
    const float* memory  = (const float*)d_in[5];   // (8192,4096)
    const float* W_ih    = (const float*)d_in[6];   // (3072,1280)
    const float* W_hh    = (const float*)d_in[7];   // (3072,1024)
    const float* b_ih    = (const float*)d_in[8];
    const float* b_hh    = (const float*)d_in[9];
    // d_in[10..19]: dead code (cosine-sim == 1, circ-conv scalar cancels in
    // sharpen, memory write discarded)
    const float* W_gamma = (const float*)d_in[20];
    const float* b_gamma = (const float*)d_in[21];
    const float* W_gate  = (const float*)d_in[22];
    const float* b_gate  = (const float*)d_in[23];

    float* out = (float*)d_out;
    // Layout: [0:4096) read_vector | [4096:12288) read_weight |
    //         [12288:20480) write_weight | [20480:21504) new_controller_hidden

    fused_kernel<<<NBLK, 1024>>>(action, hid, prev_r, prev_w, hprev, memory,
                                 W_ih, W_hh, b_ih, b_hh,
                                 W_gamma, b_gamma, W_gate, b_gate, out);
}

// round 12
// speedup vs baseline: 1.6393x; 1.1121x over previous
#include <cuda_runtime.h>

#define NDIM 8192
#define MDIM 4096
#define CDIM 1024
#define ADIM 256
#define XDIM 1280
#define NBLK 148
#define ROWS_PER 56
#define NWARPS (NBLK * 32)        // 4736
#define NPIECE (2 * 6 * CDIM)     // 12288 half-rows

// Scratch (static device globals — no runtime allocation)
__device__ float g_dots_h[NPIECE];        // half-row GRU dot partials
__device__ float g_pr[NDIM];              // unnormalized pow(read)
__device__ float g_pw[NDIM];              // unnormalized pow(write)
__device__ float g_spr[NBLK];             // per-block pow sums
__device__ float g_spw[NBLK];
__device__ float g_partial[NBLK * MDIM];  // gemv partials
__device__ unsigned g_bar1, g_bar2;

// Ticket barrier: never resets, correct across unlimited graph replays.
__device__ __forceinline__ void grid_sync(unsigned* bar) {
    __syncthreads();
    if (threadIdx.x == 0) {
        __threadfence();
        unsigned t = atomicAdd(bar, 1u);
        unsigned target = (t / NBLK + 1u) * NBLK;
        while (*(volatile unsigned*)bar < target) __nanosleep(32);
    }
    __syncthreads();
    __threadfence();
}

__global__ void __launch_bounds__(1024, 1) fused_kernel(
    const float* __restrict__ action, const float* __restrict__ hid,
    const float* __restrict__ prev_r, const float* __restrict__ prev_w,
    const float* __restrict__ hprev, const float* __restrict__ mem,
    const float* __restrict__ W_ih, const float* __restrict__ W_hh,
    const float* __restrict__ b_ih, const float* __restrict__ b_hh,
    const float* __restrict__ W_gamma, const float* __restrict__ b_gamma,
    const float* __restrict__ W_gate, const float* __restrict__ b_gate,
    float* __restrict__ out)
{
    const int tid = threadIdx.x;
    const int b   = blockIdx.x;

    __shared__ float4 smt[128][8];            // 16 KB column-reduce tree
    __shared__ float  h_s[CDIM];              // 4 KB: full GRU output
    __shared__ float  s_a[CDIM], s_b[CDIM];   // 8 KB: reduce trees
    __shared__ float  w_s[ROWS_PER];
    __shared__ float  sh_gate, sh_gamma, sh_invSr, sh_invSw;

    // ============ Phase 1: GRU dot products over half-rows =================
    // 12288 pieces (row = p>>1, half = p&1). W_ih half = 160 f4 (5/lane),
    // W_hh half = 128 f4 (4/lane). Warp w takes p = w, w+4736, w+9472.
    {
        const int lane = tid & 31;
        const int wg   = b * 32 + (tid >> 5);
        const float4* a4 = (const float4*)action;   // 64 groups
        const float4* x4 = (const float4*)hid;      // 256 groups
        const float4* h4 = (const float4*)hprev;    // 256 groups
        for (int p = wg; p < NPIECE; p += NWARPS) {
            int r  = p >> 1;
            int hf = p & 1;
            float s = 0.f;
            if (r < 3 * CDIM) {
                const float4* row = (const float4*)(W_ih + (size_t)r * XDIM);
                int base = hf * 160 + lane;
#pragma unroll
                for (int k = 0; k < 5; k++) {
                    int k4 = base + k * 32;
                    float4 rv = __ldcs(&row[k4]);
                    float4 xv = (k4 < ADIM / 4) ? a4[k4] : x4[k4 - ADIM / 4];
                    s += rv.x * xv.x + rv.y * xv.y + rv.z * xv.z + rv.w * xv.w;
                }
            } else {
                const float4* row = (const float4*)(W_hh + (size_t)(r - 3 * CDIM) * CDIM);
                int base = hf * 128 + lane;
#pragma unroll
                for (int k = 0; k < 4; k++) {
                    int k4 = base + k * 32;
                    float4 rv = __ldcs(&row[k4]);
                    float4 xv = h4[k4];
                    s += rv.x * xv.x + rv.y * xv.y + rv.z * xv.z + rv.w * xv.w;
                }
            }
#pragma unroll
            for (int off = 16; off > 0; off >>= 1)
                s += __shfl_down_sync(0xffffffffu, s, off);
            if (lane == 0) g_dots_h[p] = s;
        }
    }
    grid_sync(&g_bar1);

    // == Phase 2: every block computes all h + gate/gamma (bit-identical) ===
    {
        int c = tid;   // 1024 channels, one per thread
        float d0 = g_dots_h[2 * c]                  + g_dots_h[2 * c + 1];
        float d1 = g_dots_h[2 * (CDIM + c)]         + g_dots_h[2 * (CDIM + c) + 1];
        float d2 = g_dots_h[2 * (2 * CDIM + c)]     + g_dots_h[2 * (2 * CDIM + c) + 1];
        float d3 = g_dots_h[2 * (3 * CDIM + c)]     + g_dots_h[2 * (3 * CDIM + c) + 1];
        float d4 = g_dots_h[2 * (4 * CDIM + c)]     + g_dots_h[2 * (4 * CDIM + c) + 1];
        float d5 = g_dots_h[2 * (5 * CDIM + c)]     + g_dots_h[2 * (5 * CDIM + c) + 1];
        float hp = hprev[c];
        float r = 1.f / (1.f + expf(-(d0 + b_ih[c] + d3 + b_hh[c])));
        float z = 1.f / (1.f + expf(-(d1 + b_ih[CDIM + c] + d4 + b_hh[CDIM + c])));
        float n = tanhf(d2 + b_ih[2 * CDIM + c] + r * (d5 + b_hh[2 * CDIM + c]));
        float h = (1.f - z) * n + z * hp;
        h_s[c] = h;
        if (b == 0) out[MDIM + 2 * NDIM + c] = h;   // new_controller_hidden

        s_a[tid] = W_gate[c] * h;
        s_b[tid] = W_gamma[c] * h;
        __syncthreads();
        for (int off = 512; off > 0; off >>= 1) {
            if (tid < off) { s_a[tid] += s_a[tid + off]; s_b[tid] += s_b[tid + off]; }
            __syncthreads();
        }
        if (tid == 0) {
            sh_gate = 1.f / (1.f + expf(-(s_a[0] + b_gate[0])));
            float x = s_b[0] + b_gamma[0];
            sh_gamma = (x > 20.f) ? x : log1pf(expf(x));   // softplus
        }
        __syncthreads();
    }

    // ======== Phase 3: pow weights + streaming GEMV over own rows ==========
    const int r0 = b * ROWS_PER;
    int nrows = NDIM - r0;
    if (nrows > ROWS_PER) nrows = ROWS_PER;
    if (nrows < 0) nrows = 0;

    {
        float gate = sh_gate, gamma = sh_gamma;
        if (tid < nrows) {
            int r = r0 + tid;
            float vr = gate + (1.f - gate) * prev_r[r];
            float vw = gate + (1.f - gate) * prev_w[r];
            float pr = powf(vr, gamma);
            float pw = powf(vw, gamma);
            g_pr[r] = pr; g_pw[r] = pw;
            w_s[tid] = pr;              // unnormalized weights drive the gemv
            s_a[tid] = pr; s_b[tid] = pw;
        }
        __syncthreads();
        if (tid == 0) {
            float sa = 0.f, sb = 0.f;
            for (int j = 0; j < nrows; j++) { sa += s_a[j]; sb += s_b[j]; }
            g_spr[b] = sa; g_spw[b] = sb;
        }

        if (nrows == ROWS_PER) {        // all full blocks (b < 146)
            const float4* m4 = (const float4*)mem + (size_t)r0 * (MDIM / 4) + tid;
            float4 acc0 = make_float4(0.f, 0.f, 0.f, 0.f);
            float4 acc1 = make_float4(0.f, 0.f, 0.f, 0.f);
#pragma unroll 1
            for (int i = 0; i < ROWS_PER; i += 8) {
                float4 v[8];
                float  w[8];
#pragma unroll
                for (int j = 0; j < 8; j++) {
                    v[j] = __ldcs(m4 + (size_t)(i + j) * (MDIM / 4));
                    w[j] = w_s[i + j];
                }
#pragma unroll
                for (int j = 0; j < 8; j += 2) {
                    acc0.x += w[j] * v[j].x; acc0.y += w[j] * v[j].y;
                    acc0.z += w[j] * v[j].z; acc0.w += w[j] * v[j].w;
                    acc1.x += w[j+1] * v[j+1].x; acc1.y += w[j+1] * v[j+1].y;
                    acc1.z += w[j+1] * v[j+1].z; acc1.w += w[j+1] * v[j+1].w;
                }
            }
            acc0.x += acc1.x; acc0.y += acc1.y; acc0.z += acc1.z; acc0.w += acc1.w;
            ((float4*)g_partial)[(size_t)b * (MDIM / 4) + tid] = acc0;
        } else {                         // tail blocks (b=146: 40 rows, b=147: 0)
            const float4* m4 = (const float4*)mem + (size_t)r0 * (MDIM / 4) + tid;
            float4 acc0 = make_float4(0.f, 0.f, 0.f, 0.f);
            for (int i = 0; i < nrows; i++) {
                float w0 = w_s[i];
                float4 v0 = __ldcs(m4 + (size_t)i * (MDIM / 4));
                acc0.x += w0 * v0.x; acc0.y += w0 * v0.y;
                acc0.z += w0 * v0.z; acc0.w += w0 * v0.w;
            }
            ((float4*)g_partial)[(size_t)b * (MDIM / 4) + tid] = acc0;
        }
    }
    grid_sync(&g_bar2);

    // ================= Phase 4: normalize + column reduce ==================
    {
        if (tid < 256) {
            s_a[tid] = (tid < NBLK) ? g_spr[tid] : 0.f;
            s_b[tid] = (tid < NBLK) ? g_spw[tid] : 0.f;
        }
        __syncthreads();
        for (int off = 128; off > 0; off >>= 1) {
            if (tid < off && tid < 256) { s_a[tid] += s_a[tid + off]; s_b[tid] += s_b[tid + off]; }
            __syncthreads();
        }
        if (tid == 0) { sh_invSr = 1.f / s_a[0]; sh_invSw = 1.f / s_b[0]; }
        __syncthreads();
        float invSr = sh_invSr, invSw = sh_invSw;

        if (tid < nrows) {
            int r = r0 + tid;
            out[MDIM + r]        = g_pr[r] * invSr;  // read_weight
            out[MDIM + NDIM + r] = g_pw[r] * invSw;  // write_weight
        }

        // read_vector: blocks 0..127 each own 8 float4 column groups
        if (b < 128) {
            int cl    = tid & 7;
            int slice = tid >> 3;                    // 0..127
            int g4    = b * 8 + cl;
            const float4* p4 = (const float4*)g_partial + g4;
            float4 acc = make_float4(0.f, 0.f, 0.f, 0.f);
            for (int r = slice; r < NBLK; r += 128) {
                float4 v = p4[(size_t)r * (MDIM / 4)];
                acc.x += v.x; acc.y += v.y; acc.z += v.z; acc.w += v.w;
            }
            smt[slice][cl] = acc;
            __syncthreads();
            for (int off = 64; off > 0; off >>= 1) {
                if (slice < off) {
                    float4 a = smt[slice][cl];
                    float4 c = smt[slice + off][cl];
                    a.x += c.x; a.y += c.y; a.z += c.z; a.w += c.w;
                    smt[slice][cl] = a;
                }
                __syncthreads();
            }
            if (slice == 0) {
                float4 a = smt[0][cl];
                a.x *= invSr; a.y *= invSr; a.z *= invSr; a.w *= invSr;
                ((float4*)out)[g4] = a;              // read_vector
            }
        }
    }
}

extern "C" void kernel_launch(void* const* d_in, const int* in_sizes, int n_in,
                              void* d_out, int out_size)
{
    const float* action  = (const float*)d_in[0];   // (1,256)
    const float* hid     = (const float*)d_in[1];   // (1,1,1024)
    const float* prev_r  = (const float*)d_in[2];   // (8192,1)
    const float* prev_w  = (const float*)d_in[3];   // (8192,1)
    const float* hprev   = (const float*)d_in[4];   // (1,1,1024)
    const float* memory  = (const float*)d_in[5];   // (8192,4096)
    const float* W_ih    = (const float*)d_in[6];   // (3072,1280)
    const float* W_hh    = (const float*)d_in[7];   // (3072,1024)
    const float* b_ih    = (const float*)d_in[8];
    const float* b_hh    = (const float*)d_in[9];
    // d_in[10..19]: dead code (cosine-sim == 1, circ-conv scalar cancels in
    // sharpen, memory write discarded)
    const float* W_gamma = (const float*)d_in[20];
    const float* b_gamma = (const float*)d_in[21];
    const float* W_gate  = (const float*)d_in[22];
    const float* b_gate  = (const float*)d_in[23];

    float* out = (float*)d_out;
    // Layout: [0:4096) read_vector | [4096:12288) read_weight |
    //         [12288:20480) write_weight | [20480:21504) new_controller_hidden

    fused_kernel<<<NBLK, 1024>>>(action, hid, prev_r, prev_w, hprev, memory,
                                 W_ih, W_hh, b_ih, b_hh,
                                 W_gamma, b_gamma, W_gate, b_gate, out);
}